// round 3
// baseline (speedup 1.0000x reference)
#include <cuda_runtime.h>
#include <math.h>

#define Bb   2
#define Ss   2048
#define Dd   2048
#define Hh   16
#define KVHh 4
#define HDd  128

// ---------------- scratch (static device globals; no allocs) ----------------
__device__ float g_q[Bb * Ss * Dd];            // [B,S,H,HD]  32 MB
__device__ float g_k[Bb * Ss * KVHh * HDd];    // [B,S,KVH,HD] 8 MB
__device__ float g_v[Bb * Ss * KVHh * HDd];    // 8 MB
__device__ float g_attn[Bb * Ss * Dd];         // [B,S,D]     32 MB
__device__ float g_cos[Ss * 64];
__device__ float g_sin[Ss * 64];

// ---------------- RoPE table (match reference fp32 angle, accurate trig) ----
__global__ void rope_table_kernel() {
    int i = blockIdx.x * blockDim.x + threadIdx.x;
    if (i >= Ss * 64) return;
    int s = i >> 6, j = i & 63;
    float e   = (float)(2 * j) / (float)HDd;
    float inv = 1.0f / powf(10000.0f, e);
    float ang = (float)s * inv;          // fp32 angle like the reference
    g_cos[i] = (float)cos((double)ang);
    g_sin[i] = (float)sin((double)ang);
}

// ---------------- SGEMM: C[m,n] = sum_k A[m,k] * B[n,k] --------------------
// A: [M,K] row-major, B: [N,K] row-major (i.e. C = A @ B^T). 128x128x8 tile,
// 256 threads, 8x8 microtile with interleaved (t + 16*i) mapping => LDS
// conflict-free without padding. All dims divide tile sizes for this problem.
__global__ __launch_bounds__(256) void sgemm_nt(const float* __restrict__ A,
                                                const float* __restrict__ B,
                                                float* __restrict__ C,
                                                int M, int N, int K) {
    __shared__ float As[8][128];
    __shared__ float Bs[8][128];
    const int tid = threadIdx.x;
    const int tx = tid & 15, ty = tid >> 4;
    const int bm = blockIdx.y * 128, bn = blockIdx.x * 128;
    const int lrow = tid >> 1;
    const int lk4  = (tid & 1) * 4;
    const float* Ap = A + (size_t)(bm + lrow) * K + lk4;
    const float* Bp = B + (size_t)(bn + lrow) * K + lk4;

    float acc[8][8];
#pragma unroll
    for (int i = 0; i < 8; i++)
#pragma unroll
        for (int j = 0; j < 8; j++) acc[i][j] = 0.0f;

    for (int k0 = 0; k0 < K; k0 += 8) {
        float4 av = *(const float4*)(Ap + k0);
        float4 bv = *(const float4*)(Bp + k0);
        As[lk4 + 0][lrow] = av.x; As[lk4 + 1][lrow] = av.y;
        As[lk4 + 2][lrow] = av.z; As[lk4 + 3][lrow] = av.w;
        Bs[lk4 + 0][lrow] = bv.x; Bs[lk4 + 1][lrow] = bv.y;
        Bs[lk4 + 2][lrow] = bv.z; Bs[lk4 + 3][lrow] = bv.w;
        __syncthreads();
#pragma unroll
        for (int kk = 0; kk < 8; kk++) {
            float a[8], b[8];
#pragma unroll
            for (int i = 0; i < 8; i++) a[i] = As[kk][ty + 16 * i];
#pragma unroll
            for (int j = 0; j < 8; j++) b[j] = Bs[kk][tx + 16 * j];
#pragma unroll
            for (int i = 0; i < 8; i++)
#pragma unroll
                for (int j = 0; j < 8; j++) acc[i][j] += a[i] * b[j];
        }
        __syncthreads();
    }
#pragma unroll
    for (int i = 0; i < 8; i++)
#pragma unroll
        for (int j = 0; j < 8; j++)
            C[(size_t)(bm + ty + 16 * i) * N + (bn + tx + 16 * j)] = acc[i][j];
}

// ---------------- q epilogue: RMSNorm + RoPE + gain/sqrt(HD) ----------------
// one warp per (b,s,h) head vector of 128; lanes hold elems {l, l+32, l+64, l+96}
__global__ __launch_bounds__(256) void q_post(const float* __restrict__ gain) {
    int wid  = blockIdx.x * 8 + (threadIdx.x >> 5);   // 0 .. B*S*H-1
    int lane = threadIdx.x & 31;
    int h = wid & (Hh - 1);
    int s = (wid >> 4) & (Ss - 1);
    float* base = g_q + (size_t)wid * 128;
    float e0 = base[lane], e1 = base[lane + 32], e2 = base[lane + 64], e3 = base[lane + 96];
    float ssum = e0 * e0 + e1 * e1 + e2 * e2 + e3 * e3;
#pragma unroll
    for (int o = 16; o > 0; o >>= 1) ssum += __shfl_xor_sync(0xffffffffu, ssum, o);
    float r = rsqrtf(ssum * (1.0f / 128.0f) + 1e-6f);
    float g = gain[h] * r * 0.08838834764831845f;     // gain * rmsnorm * 1/sqrt(128)
    float c0 = g_cos[s * 64 + lane],      sn0 = g_sin[s * 64 + lane];
    float c1 = g_cos[s * 64 + lane + 32], sn1 = g_sin[s * 64 + lane + 32];
    base[lane]      = ( e0 * c0  + e2 * sn0) * g;
    base[lane + 32] = ( e1 * c1  + e3 * sn1) * g;
    base[lane + 64] = (-e0 * sn0 + e2 * c0 ) * g;
    base[lane + 96] = (-e1 * sn1 + e3 * c1 ) * g;
}

__global__ __launch_bounds__(256) void k_post() {
    int wid  = blockIdx.x * 8 + (threadIdx.x >> 5);   // 0 .. B*S*KVH-1
    int lane = threadIdx.x & 31;
    int s = (wid >> 2) & (Ss - 1);
    float* base = g_k + (size_t)wid * 128;
    float e0 = base[lane], e1 = base[lane + 32], e2 = base[lane + 64], e3 = base[lane + 96];
    float ssum = e0 * e0 + e1 * e1 + e2 * e2 + e3 * e3;
#pragma unroll
    for (int o = 16; o > 0; o >>= 1) ssum += __shfl_xor_sync(0xffffffffu, ssum, o);
    float r = rsqrtf(ssum * (1.0f / 128.0f) + 1e-6f);
    float c0 = g_cos[s * 64 + lane],      sn0 = g_sin[s * 64 + lane];
    float c1 = g_cos[s * 64 + lane + 32], sn1 = g_sin[s * 64 + lane + 32];
    base[lane]      = ( e0 * c0  + e2 * sn0) * r;
    base[lane + 32] = ( e1 * c1  + e3 * sn1) * r;
    base[lane + 64] = (-e0 * sn0 + e2 * c0 ) * r;
    base[lane + 96] = (-e1 * sn1 + e3 * c1 ) * r;
}

// ---------------- flash attention (fp32, online softmax) -------------------
// Block: one (b, h, q-tile of 64). 256 threads as (tx,ty) in 16x16.
// smem strides padded (129 / 65) => conflict-free inner-loop LDS.
#define FL_SMEM ((3 * 64 * 129 + 64 * 65) * 4)

__global__ __launch_bounds__(256) void flash_kernel() {
    extern __shared__ float sm[];
    float* Qs = sm;                  // 64 x 129
    float* Ks = sm + 64 * 129;       // 64 x 129
    float* Vs = sm + 2 * 64 * 129;   // 64 x 129
    float* Ps = sm + 3 * 64 * 129;   // 64 x 65

    const int tid = threadIdx.x;
    const int tx = tid & 15, ty = tid >> 4;
    const int qt = (Ss / 64 - 1) - blockIdx.x;   // big tiles first (wave balance)
    const int h  = blockIdx.y;
    const int b  = blockIdx.z;
    const int kvh = h >> 2;                      // H/KVH = 4
    const int q0 = qt * 64;

    // load Q tile (resident whole block)
    for (int i = tid; i < 64 * 128; i += 256) {
        int r = i >> 7, d = i & 127;
        Qs[r * 129 + d] = g_q[((size_t)((b * Ss + q0 + r) * Hh + h)) * HDd + d];
    }

    float m_i[4], l_i[4], O[4][8];
#pragma unroll
    for (int i = 0; i < 4; i++) {
        m_i[i] = -1e30f; l_i[i] = 0.0f;
#pragma unroll
        for (int j = 0; j < 8; j++) O[i][j] = 0.0f;
    }
    __syncthreads();

    for (int kt = 0; kt <= qt; kt++) {
        const int k0 = kt * 64;
        // load K,V tiles (float4 gmem, scalar STS into padded rows)
        for (int i = tid; i < 64 * 32; i += 256) {
            int r = i >> 5, c4 = (i & 31) << 2;
            size_t goff = ((size_t)((b * Ss + k0 + r) * KVHh + kvh)) * HDd + c4;
            float4 kv4 = *(const float4*)(g_k + goff);
            float4 vv4 = *(const float4*)(g_v + goff);
            float* kr = Ks + r * 129 + c4;
            float* vr = Vs + r * 129 + c4;
            kr[0] = kv4.x; kr[1] = kv4.y; kr[2] = kv4.z; kr[3] = kv4.w;
            vr[0] = vv4.x; vr[1] = vv4.y; vr[2] = vv4.z; vr[3] = vv4.w;
        }
        __syncthreads();

        // S = Q . K^T  (q already carries gain/sqrt(HD))
        float acc[4][4];
#pragma unroll
        for (int i = 0; i < 4; i++)
#pragma unroll
            for (int j = 0; j < 4; j++) acc[i][j] = 0.0f;
#pragma unroll 8
        for (int kk = 0; kk < 128; kk++) {
            float qr[4], kr[4];
#pragma unroll
            for (int i = 0; i < 4; i++) qr[i] = Qs[(ty + 16 * i) * 129 + kk];
#pragma unroll
            for (int j = 0; j < 4; j++) kr[j] = Ks[(tx + 16 * j) * 129 + kk];
#pragma unroll
            for (int i = 0; i < 4; i++)
#pragma unroll
                for (int j = 0; j < 4; j++) acc[i][j] += qr[i] * kr[j];
        }

        if (kt == qt) {   // diagonal tile: mask c > r
#pragma unroll
            for (int i = 0; i < 4; i++)
#pragma unroll
                for (int j = 0; j < 4; j++)
                    if (tx + 16 * j > ty + 16 * i) acc[i][j] = -1e30f;
        }

        // online softmax per row (rows ty+16i shared by the 16-lane half-warp)
#pragma unroll
        for (int i = 0; i < 4; i++) {
            float tm = acc[i][0];
#pragma unroll
            for (int j = 1; j < 4; j++) tm = fmaxf(tm, acc[i][j]);
#pragma unroll
            for (int o = 8; o > 0; o >>= 1) tm = fmaxf(tm, __shfl_xor_sync(0xffffffffu, tm, o));
            float mnew  = fmaxf(m_i[i], tm);
            float alpha = expf(m_i[i] - mnew);
            float ps = 0.0f;
#pragma unroll
            for (int j = 0; j < 4; j++) {
                float p = expf(acc[i][j] - mnew);
                Ps[(ty + 16 * i) * 65 + (tx + 16 * j)] = p;
                ps += p;
            }
#pragma unroll
            for (int o = 8; o > 0; o >>= 1) ps += __shfl_xor_sync(0xffffffffu, ps, o);
            l_i[i] = l_i[i] * alpha + ps;
#pragma unroll
            for (int j = 0; j < 8; j++) O[i][j] *= alpha;
            m_i[i] = mnew;
        }
        __syncthreads();

        // O += P . V
#pragma unroll 4
        for (int kk = 0; kk < 64; kk++) {
            float pr[4], vv[8];
#pragma unroll
            for (int i = 0; i < 4; i++) pr[i] = Ps[(ty + 16 * i) * 65 + kk];
#pragma unroll
            for (int j = 0; j < 8; j++) vv[j] = Vs[kk * 129 + (tx + 16 * j)];
#pragma unroll
            for (int i = 0; i < 4; i++)
#pragma unroll
                for (int j = 0; j < 8; j++) O[i][j] += pr[i] * vv[j];
        }
        __syncthreads();   // before next tile overwrites Ks/Vs/Ps
    }

    // epilogue: normalize and store [B,S,D] with head h at cols h*128..
#pragma unroll
    for (int i = 0; i < 4; i++) {
        float inv = 1.0f / l_i[i];
#pragma unroll
        for (int j = 0; j < 8; j++)
            g_attn[(size_t)(b * Ss + q0 + ty + 16 * i) * Dd + h * HDd + (tx + 16 * j)]
                = O[i][j] * inv;
    }
}

// ---------------- launch ----------------------------------------------------
extern "C" void kernel_launch(void* const* d_in, const int* in_sizes, int n_in,
                              void* d_out, int out_size) {
    const float* x    = (const float*)d_in[0];
    const float* Wq   = (const float*)d_in[1];
    const float* Wk   = (const float*)d_in[2];
    const float* Wv   = (const float*)d_in[3];
    const float* Wp   = (const float*)d_in[4];
    const float* gain = (const float*)d_in[5];
    float* out = (float*)d_out;

    float *q, *k, *v, *attn;
    cudaGetSymbolAddress((void**)&q,    g_q);
    cudaGetSymbolAddress((void**)&k,    g_k);
    cudaGetSymbolAddress((void**)&v,    g_v);
    cudaGetSymbolAddress((void**)&attn, g_attn);

    cudaFuncSetAttribute(flash_kernel, cudaFuncAttributeMaxDynamicSharedMemorySize, FL_SMEM);

    const int M = Bb * Ss;  // 4096

    rope_table_kernel<<<(Ss * 64 + 255) / 256, 256>>>();

    sgemm_nt<<<dim3(Dd / 128, M / 128), 256>>>(x, Wq, q, M, Dd, Dd);
    sgemm_nt<<<dim3((KVHh * HDd) / 128, M / 128), 256>>>(x, Wk, k, M, KVHh * HDd, Dd);
    sgemm_nt<<<dim3((KVHh * HDd) / 128, M / 128), 256>>>(x, Wv, v, M, KVHh * HDd, Dd);

    q_post<<<(Bb * Ss * Hh) / 8, 256>>>(gain);
    k_post<<<(Bb * Ss * KVHh) / 8, 256>>>();

    flash_kernel<<<dim3(Ss / 64, Hh, Bb), 256, FL_SMEM>>>();

    sgemm_nt<<<dim3(Dd / 128, M / 128), 256>>>(attn, Wp, out, M, Dd, Dd);
}

// round 7
// speedup vs baseline: 1.7979x; 1.7979x over previous
#include <cuda_runtime.h>
#include <cuda_bf16.h>
#include <math.h>
#include <stdint.h>

#define Bb   2
#define Ss   2048
#define Dd   2048
#define Hh   16
#define KVHh 4
#define HDd  128

typedef __nv_bfloat16 bf16;

// ---------------- scratch (static device globals; no allocs) ----------------
__device__ float g_q[Bb * Ss * Dd];            // [B,S,H,HD]  32 MB
__device__ float g_k[Bb * Ss * KVHh * HDd];    // 8 MB
__device__ float g_v[Bb * Ss * KVHh * HDd];    // 8 MB
__device__ float g_attn[Bb * Ss * Dd];         // 32 MB
__device__ float g_cos[Ss * 64];
__device__ float g_sin[Ss * 64];
// split-bf16 operand scratch (xh/xl reused for attn before the out-proj)
__device__ __align__(16) bf16 g_xh[Bb * Ss * Dd];
__device__ __align__(16) bf16 g_xl[Bb * Ss * Dd];
__device__ __align__(16) bf16 g_wh[Dd * Dd];
__device__ __align__(16) bf16 g_wl[Dd * Dd];

// ---------------- helpers ----------------------------------------------------
__device__ __forceinline__ uint32_t smem_u32(const void* p) {
    uint32_t a;
    asm("{ .reg .u64 t; cvta.to.shared.u64 t, %1; cvt.u32.u64 %0, t; }" : "=r"(a) : "l"(p));
    return a;
}
#define CP_ASYNC16(dst, src) \
    asm volatile("cp.async.cg.shared.global [%0], [%1], 16;" :: "r"(dst), "l"(src) : "memory")
#define CP_COMMIT()  asm volatile("cp.async.commit_group;" ::: "memory")
#define CP_WAIT1()   asm volatile("cp.async.wait_group 1;" ::: "memory")
#define CP_WAIT0()   asm volatile("cp.async.wait_group 0;" ::: "memory")

__device__ __forceinline__ void mma16816(float* d, const uint32_t* a, const uint32_t* b) {
    asm volatile("mma.sync.aligned.m16n8k16.row.col.f32.bf16.bf16.f32 "
        "{%0,%1,%2,%3}, {%4,%5,%6,%7}, {%8,%9}, {%0,%1,%2,%3};"
        : "+f"(d[0]), "+f"(d[1]), "+f"(d[2]), "+f"(d[3])
        : "r"(a[0]), "r"(a[1]), "r"(a[2]), "r"(a[3]), "r"(b[0]), "r"(b[1]));
}

// ---------------- RoPE table ------------------------------------------------
__global__ void rope_table_kernel() {
    int i = blockIdx.x * blockDim.x + threadIdx.x;
    if (i >= Ss * 64) return;
    int s = i >> 6, j = i & 63;
    float e   = (float)(2 * j) / (float)HDd;
    float inv = 1.0f / powf(10000.0f, e);
    float ang = (float)s * inv;
    g_cos[i] = (float)cos((double)ang);
    g_sin[i] = (float)sin((double)ang);
}

// ---------------- fp32 -> bf16 hi/lo split ----------------------------------
__global__ __launch_bounds__(256) void cvt_split(const float* __restrict__ src,
                                                 bf16* __restrict__ hi,
                                                 bf16* __restrict__ lo, int n4) {
    int i = blockIdx.x * blockDim.x + threadIdx.x;
    if (i >= n4) return;
    float4 v = ((const float4*)src)[i];
    bf16 h0 = __float2bfloat16(v.x), h1 = __float2bfloat16(v.y);
    bf16 h2 = __float2bfloat16(v.z), h3 = __float2bfloat16(v.w);
    bf16 l0 = __float2bfloat16(v.x - __bfloat162float(h0));
    bf16 l1 = __float2bfloat16(v.y - __bfloat162float(h1));
    bf16 l2 = __float2bfloat16(v.z - __bfloat162float(h2));
    bf16 l3 = __float2bfloat16(v.w - __bfloat162float(h3));
    ((__nv_bfloat162*)hi)[2 * i]     = __halves2bfloat162(h0, h1);
    ((__nv_bfloat162*)hi)[2 * i + 1] = __halves2bfloat162(h2, h3);
    ((__nv_bfloat162*)lo)[2 * i]     = __halves2bfloat162(l0, l1);
    ((__nv_bfloat162*)lo)[2 * i + 1] = __halves2bfloat162(l2, l3);
}

// ---------------- split-bf16 HMMA GEMM: C = A @ B^T -------------------------
// A: [M,K], B: [N,K] row-major bf16 (hi/lo). CTA tile 128x128, K-chunk 32.
// 8 warps as 2(M) x 4(N); warp tile 64x32; mma m16n8k16; fp32 accumulators.
// smem rows padded to 40 bf16 (80B) -> fragment LDS bank-conflict-free.
#define LDA        40
#define ARRB       (128 * LDA * 2)          // 10240 bytes per operand array
#define STAGEB     (4 * ARRB)               // 40960 bytes per stage
#define GEMM_SMEM  (2 * STAGEB)             // 81920 bytes

__device__ __forceinline__ void gemm_load_chunk(
    uint32_t sm32, int buf, int tid, int c,
    const bf16* __restrict__ Ah, const bf16* __restrict__ Al,
    const bf16* __restrict__ Bh, const bf16* __restrict__ Bl,
    int bm, int bn, int K) {
    int row = tid >> 2;            // 0..63  (also +64)
    int t16 = tid & 3;             // 16B chunk within 64B row
    uint32_t so = sm32 + buf * STAGEB + (uint32_t)row * 80 + (uint32_t)t16 * 16;
    size_t gA = (size_t)(bm + row) * K + (size_t)c * 32 + t16 * 8;
    size_t gB = (size_t)(bn + row) * K + (size_t)c * 32 + t16 * 8;
    size_t stp = (size_t)64 * K;
    CP_ASYNC16(so,                       Ah + gA);
    CP_ASYNC16(so + 64 * 80,             Ah + gA + stp);
    CP_ASYNC16(so + ARRB,                Al + gA);
    CP_ASYNC16(so + ARRB + 64 * 80,      Al + gA + stp);
    CP_ASYNC16(so + 2 * ARRB,            Bh + gB);
    CP_ASYNC16(so + 2 * ARRB + 64 * 80,  Bh + gB + stp);
    CP_ASYNC16(so + 3 * ARRB,            Bl + gB);
    CP_ASYNC16(so + 3 * ARRB + 64 * 80,  Bl + gB + stp);
}

__global__ __launch_bounds__(256) void gemm_bf16s(
    const bf16* __restrict__ Ah, const bf16* __restrict__ Al,
    const bf16* __restrict__ Bh, const bf16* __restrict__ Bl,
    float* __restrict__ C, int M, int N, int K) {
    extern __shared__ char sm[];
    const uint32_t sm32 = smem_u32(sm);
    const int tid  = threadIdx.x;
    const int wid  = tid >> 5, lane = tid & 31;
    const int lr   = lane >> 2, lc = lane & 3;
    const int wm   = wid & 1;            // 0..1 -> M offset wm*64
    const int wn   = wid >> 1;           // 0..3 -> N offset wn*32
    const int bm = blockIdx.y * 128, bn = blockIdx.x * 128;

    float acc[4][4][4];
#pragma unroll
    for (int i = 0; i < 4; i++)
#pragma unroll
        for (int j = 0; j < 4; j++)
#pragma unroll
            for (int r = 0; r < 4; r++) acc[i][j][r] = 0.0f;

    const int NC = K >> 5;
    gemm_load_chunk(sm32, 0, tid, 0, Ah, Al, Bh, Bl, bm, bn, K);
    CP_COMMIT();

    for (int c = 0; c < NC; c++) {
        const int buf = c & 1;
        if (c + 1 < NC) {
            gemm_load_chunk(sm32, buf ^ 1, tid, c + 1, Ah, Al, Bh, Bl, bm, bn, K);
            CP_COMMIT();
            CP_WAIT1();
        } else {
            CP_WAIT0();
        }
        __syncthreads();

        const bf16* sA = (const bf16*)(sm + buf * STAGEB);
        const bf16* sAl = sA + 128 * LDA;
        const bf16* sB  = sA + 2 * 128 * LDA;
        const bf16* sBl = sA + 3 * 128 * LDA;
#pragma unroll
        for (int kst = 0; kst < 2; kst++) {
            const int pp = kst * 8 + lc;
            uint32_t ah[4][4], al[4][4], bh[4][2], bl[4][2];
#pragma unroll
            for (int mt = 0; mt < 4; mt++) {
                int r0 = wm * 64 + mt * 16 + lr;
                ah[mt][0] = *(const uint32_t*)(sA + r0 * LDA + pp * 2);
                ah[mt][1] = *(const uint32_t*)(sA + (r0 + 8) * LDA + pp * 2);
                ah[mt][2] = *(const uint32_t*)(sA + r0 * LDA + (pp + 4) * 2);
                ah[mt][3] = *(const uint32_t*)(sA + (r0 + 8) * LDA + (pp + 4) * 2);
                al[mt][0] = *(const uint32_t*)(sAl + r0 * LDA + pp * 2);
                al[mt][1] = *(const uint32_t*)(sAl + (r0 + 8) * LDA + pp * 2);
                al[mt][2] = *(const uint32_t*)(sAl + r0 * LDA + (pp + 4) * 2);
                al[mt][3] = *(const uint32_t*)(sAl + (r0 + 8) * LDA + (pp + 4) * 2);
            }
#pragma unroll
            for (int nt = 0; nt < 4; nt++) {
                int n0 = wn * 32 + nt * 8 + lr;
                bh[nt][0] = *(const uint32_t*)(sB + n0 * LDA + pp * 2);
                bh[nt][1] = *(const uint32_t*)(sB + n0 * LDA + (pp + 4) * 2);
                bl[nt][0] = *(const uint32_t*)(sBl + n0 * LDA + pp * 2);
                bl[nt][1] = *(const uint32_t*)(sBl + n0 * LDA + (pp + 4) * 2);
            }
#pragma unroll
            for (int mt = 0; mt < 4; mt++)
#pragma unroll
                for (int nt = 0; nt < 4; nt++) {
                    mma16816(acc[mt][nt], ah[mt], bh[nt]);   // Ah*Bh
                    mma16816(acc[mt][nt], ah[mt], bl[nt]);   // Ah*Bl
                    mma16816(acc[mt][nt], al[mt], bh[nt]);   // Al*Bh
                }
        }
        __syncthreads();
    }

    // epilogue: c0,c1 -> (m, n..n+1); c2,c3 -> (m+8, n..n+1)
#pragma unroll
    for (int mt = 0; mt < 4; mt++) {
        int m = bm + wm * 64 + mt * 16 + lr;
#pragma unroll
        for (int nt = 0; nt < 4; nt++) {
            int n = bn + wn * 32 + nt * 8 + lc * 2;
            float2 v0 = make_float2(acc[mt][nt][0], acc[mt][nt][1]);
            float2 v1 = make_float2(acc[mt][nt][2], acc[mt][nt][3]);
            *(float2*)(C + (size_t)m * N + n)       = v0;
            *(float2*)(C + (size_t)(m + 8) * N + n) = v1;
        }
    }
}

// ---------------- q epilogue: RMSNorm + RoPE + gain/sqrt(HD) ----------------
__global__ __launch_bounds__(256) void q_post(const float* __restrict__ gain) {
    int wid  = blockIdx.x * 8 + (threadIdx.x >> 5);
    int lane = threadIdx.x & 31;
    int h = wid & (Hh - 1);
    int s = (wid >> 4) & (Ss - 1);
    float* base = g_q + (size_t)wid * 128;
    float e0 = base[lane], e1 = base[lane + 32], e2 = base[lane + 64], e3 = base[lane + 96];
    float ssum = e0 * e0 + e1 * e1 + e2 * e2 + e3 * e3;
#pragma unroll
    for (int o = 16; o > 0; o >>= 1) ssum += __shfl_xor_sync(0xffffffffu, ssum, o);
    float r = rsqrtf(ssum * (1.0f / 128.0f) + 1e-6f);
    float g = gain[h] * r * 0.08838834764831845f;
    float c0 = g_cos[s * 64 + lane],      sn0 = g_sin[s * 64 + lane];
    float c1 = g_cos[s * 64 + lane + 32], sn1 = g_sin[s * 64 + lane + 32];
    base[lane]      = ( e0 * c0  + e2 * sn0) * g;
    base[lane + 32] = ( e1 * c1  + e3 * sn1) * g;
    base[lane + 64] = (-e0 * sn0 + e2 * c0 ) * g;
    base[lane + 96] = (-e1 * sn1 + e3 * c1 ) * g;
}

__global__ __launch_bounds__(256) void k_post() {
    int wid  = blockIdx.x * 8 + (threadIdx.x >> 5);
    int lane = threadIdx.x & 31;
    int s = (wid >> 2) & (Ss - 1);
    float* base = g_k + (size_t)wid * 128;
    float e0 = base[lane], e1 = base[lane + 32], e2 = base[lane + 64], e3 = base[lane + 96];
    float ssum = e0 * e0 + e1 * e1 + e2 * e2 + e3 * e3;
#pragma unroll
    for (int o = 16; o > 0; o >>= 1) ssum += __shfl_xor_sync(0xffffffffu, ssum, o);
    float r = rsqrtf(ssum * (1.0f / 128.0f) + 1e-6f);
    float c0 = g_cos[s * 64 + lane],      sn0 = g_sin[s * 64 + lane];
    float c1 = g_cos[s * 64 + lane + 32], sn1 = g_sin[s * 64 + lane + 32];
    base[lane]      = ( e0 * c0  + e2 * sn0) * r;
    base[lane + 32] = ( e1 * c1  + e3 * sn1) * r;
    base[lane + 64] = (-e0 * sn0 + e2 * c0 ) * r;
    base[lane + 96] = (-e1 * sn1 + e3 * c1 ) * r;
}

// ---------------- flash attention (fp32, online softmax) -------------------
#define FL_SMEM ((3 * 64 * 129 + 64 * 65) * 4)

__global__ __launch_bounds__(256) void flash_kernel() {
    extern __shared__ float smf[];
    float* Qs = smf;
    float* Ks = smf + 64 * 129;
    float* Vs = smf + 2 * 64 * 129;
    float* Ps = smf + 3 * 64 * 129;

    const int tid = threadIdx.x;
    const int tx = tid & 15, ty = tid >> 4;
    const int qt = (Ss / 64 - 1) - blockIdx.x;
    const int h  = blockIdx.y;
    const int b  = blockIdx.z;
    const int kvh = h >> 2;
    const int q0 = qt * 64;

    for (int i = tid; i < 64 * 128; i += 256) {
        int r = i >> 7, d = i & 127;
        Qs[r * 129 + d] = g_q[((size_t)((b * Ss + q0 + r) * Hh + h)) * HDd + d];
    }

    float m_i[4], l_i[4], O[4][8];
#pragma unroll
    for (int i = 0; i < 4; i++) {
        m_i[i] = -1e30f; l_i[i] = 0.0f;
#pragma unroll
        for (int j = 0; j < 8; j++) O[i][j] = 0.0f;
    }
    __syncthreads();

    for (int kt = 0; kt <= qt; kt++) {
        const int k0 = kt * 64;
        for (int i = tid; i < 64 * 32; i += 256) {
            int r = i >> 5, c4 = (i & 31) << 2;
            size_t goff = ((size_t)((b * Ss + k0 + r) * KVHh + kvh)) * HDd + c4;
            float4 kv4 = *(const float4*)(g_k + goff);
            float4 vv4 = *(const float4*)(g_v + goff);
            float* kr = Ks + r * 129 + c4;
            float* vr = Vs + r * 129 + c4;
            kr[0] = kv4.x; kr[1] = kv4.y; kr[2] = kv4.z; kr[3] = kv4.w;
            vr[0] = vv4.x; vr[1] = vv4.y; vr[2] = vv4.z; vr[3] = vv4.w;
        }
        __syncthreads();

        float acc[4][4];
#pragma unroll
        for (int i = 0; i < 4; i++)
#pragma unroll
            for (int j = 0; j < 4; j++) acc[i][j] = 0.0f;
#pragma unroll 8
        for (int kk = 0; kk < 128; kk++) {
            float qr[4], kr[4];
#pragma unroll
            for (int i = 0; i < 4; i++) qr[i] = Qs[(ty + 16 * i) * 129 + kk];
#pragma unroll
            for (int j = 0; j < 4; j++) kr[j] = Ks[(tx + 16 * j) * 129 + kk];
#pragma unroll
            for (int i = 0; i < 4; i++)
#pragma unroll
                for (int j = 0; j < 4; j++) acc[i][j] += qr[i] * kr[j];
        }

        if (kt == qt) {
#pragma unroll
            for (int i = 0; i < 4; i++)
#pragma unroll
                for (int j = 0; j < 4; j++)
                    if (tx + 16 * j > ty + 16 * i) acc[i][j] = -1e30f;
        }

#pragma unroll
        for (int i = 0; i < 4; i++) {
            float tm = acc[i][0];
#pragma unroll
            for (int j = 1; j < 4; j++) tm = fmaxf(tm, acc[i][j]);
#pragma unroll
            for (int o = 8; o > 0; o >>= 1) tm = fmaxf(tm, __shfl_xor_sync(0xffffffffu, tm, o));
            float mnew  = fmaxf(m_i[i], tm);
            float alpha = expf(m_i[i] - mnew);
            float ps = 0.0f;
#pragma unroll
            for (int j = 0; j < 4; j++) {
                float p = expf(acc[i][j] - mnew);
                Ps[(ty + 16 * i) * 65 + (tx + 16 * j)] = p;
                ps += p;
            }
#pragma unroll
            for (int o = 8; o > 0; o >>= 1) ps += __shfl_xor_sync(0xffffffffu, ps, o);
            l_i[i] = l_i[i] * alpha + ps;
#pragma unroll
            for (int j = 0; j < 8; j++) O[i][j] *= alpha;
            m_i[i] = mnew;
        }
        __syncthreads();

#pragma unroll 4
        for (int kk = 0; kk < 64; kk++) {
            float pr[4], vv[8];
#pragma unroll
            for (int i = 0; i < 4; i++) pr[i] = Ps[(ty + 16 * i) * 65 + kk];
#pragma unroll
            for (int j = 0; j < 8; j++) vv[j] = Vs[kk * 129 + (tx + 16 * j)];
#pragma unroll
            for (int i = 0; i < 4; i++)
#pragma unroll
                for (int j = 0; j < 8; j++) O[i][j] += pr[i] * vv[j];
        }
        __syncthreads();
    }

#pragma unroll
    for (int i = 0; i < 4; i++) {
        float inv = 1.0f / l_i[i];
#pragma unroll
        for (int j = 0; j < 8; j++)
            g_attn[(size_t)(b * Ss + q0 + ty + 16 * i) * Dd + h * HDd + (tx + 16 * j)]
                = O[i][j] * inv;
    }
}

// ---------------- launch ----------------------------------------------------
extern "C" void kernel_launch(void* const* d_in, const int* in_sizes, int n_in,
                              void* d_out, int out_size) {
    const float* x    = (const float*)d_in[0];
    const float* Wq   = (const float*)d_in[1];
    const float* Wk   = (const float*)d_in[2];
    const float* Wv   = (const float*)d_in[3];
    const float* Wp   = (const float*)d_in[4];
    const float* gain = (const float*)d_in[5];
    float* out = (float*)d_out;

    float *q, *k, *v, *attn;
    bf16 *xh, *xl, *wh, *wl;
    cudaGetSymbolAddress((void**)&q,    g_q);
    cudaGetSymbolAddress((void**)&k,    g_k);
    cudaGetSymbolAddress((void**)&v,    g_v);
    cudaGetSymbolAddress((void**)&attn, g_attn);
    cudaGetSymbolAddress((void**)&xh,   g_xh);
    cudaGetSymbolAddress((void**)&xl,   g_xl);
    cudaGetSymbolAddress((void**)&wh,   g_wh);
    cudaGetSymbolAddress((void**)&wl,   g_wl);

    cudaFuncSetAttribute(flash_kernel, cudaFuncAttributeMaxDynamicSharedMemorySize, FL_SMEM);
    cudaFuncSetAttribute(gemm_bf16s,  cudaFuncAttributeMaxDynamicSharedMemorySize, GEMM_SMEM);

    const int M = Bb * Ss;                 // 4096
    const int n4x = M * Dd / 4;
    const int n4w = Dd * Dd / 4;
    const int n4k = KVHh * HDd * Dd / 4;

    rope_table_kernel<<<(Ss * 64 + 255) / 256, 256>>>();

    cvt_split<<<(n4x + 255) / 256, 256>>>(x, xh, xl, n4x);

    cvt_split<<<(n4w + 255) / 256, 256>>>(Wq, wh, wl, n4w);
    gemm_bf16s<<<dim3(Dd / 128, M / 128), 256, GEMM_SMEM>>>(xh, xl, wh, wl, q, M, Dd, Dd);

    cvt_split<<<(n4k + 255) / 256, 256>>>(Wk, wh, wl, n4k);
    gemm_bf16s<<<dim3((KVHh * HDd) / 128, M / 128), 256, GEMM_SMEM>>>(xh, xl, wh, wl, k, M, KVHh * HDd, Dd);

    cvt_split<<<(n4k + 255) / 256, 256>>>(Wv, wh, wl, n4k);
    gemm_bf16s<<<dim3((KVHh * HDd) / 128, M / 128), 256, GEMM_SMEM>>>(xh, xl, wh, wl, v, M, KVHh * HDd, Dd);

    q_post<<<(Bb * Ss * Hh) / 8, 256>>>(gain);
    k_post<<<(Bb * Ss * KVHh) / 8, 256>>>();

    flash_kernel<<<dim3(Ss / 64, Hh, Bb), 256, FL_SMEM>>>();

    cvt_split<<<(n4x + 255) / 256, 256>>>(attn, xh, xl, n4x);
    cvt_split<<<(n4w + 255) / 256, 256>>>(Wp, wh, wl, n4w);
    gemm_bf16s<<<dim3(Dd / 128, M / 128), 256, GEMM_SMEM>>>(xh, xl, wh, wl, out, M, Dd, Dd);
}

// round 8
// speedup vs baseline: 3.2703x; 1.8190x over previous
#include <cuda_runtime.h>
#include <cuda_bf16.h>
#include <math.h>
#include <stdint.h>

#define Bb   2
#define Ss   2048
#define Dd   2048
#define Hh   16
#define KVHh 4
#define HDd  128

typedef __nv_bfloat16 bf16;

// ---------------- scratch (static device globals; no allocs) ----------------
__device__ float g_q[Bb * Ss * Dd];            // fp32 q after proj
__device__ float g_k[Bb * Ss * KVHh * HDd];
__device__ float g_v[Bb * Ss * KVHh * HDd];
__device__ float g_cos[Ss * 64];
__device__ float g_sin[Ss * 64];
// split-bf16 operands. xh/xl: x-split -> Q-split (post) -> attn-out-split (flash)
__device__ __align__(16) bf16 g_xh[Bb * Ss * Dd];
__device__ __align__(16) bf16 g_xl[Bb * Ss * Dd];
__device__ __align__(16) bf16 g_wh[Dd * Dd];
__device__ __align__(16) bf16 g_wl[Dd * Dd];
__device__ __align__(16) bf16 g_kh[Bb * Ss * KVHh * HDd];
__device__ __align__(16) bf16 g_kl[Bb * Ss * KVHh * HDd];
__device__ __align__(16) bf16 g_vh[Bb * Ss * KVHh * HDd];
__device__ __align__(16) bf16 g_vl[Bb * Ss * KVHh * HDd];

// ---------------- helpers ----------------------------------------------------
__device__ __forceinline__ uint32_t smem_u32(const void* p) {
    uint32_t a;
    asm("{ .reg .u64 t; cvta.to.shared.u64 t, %1; cvt.u32.u64 %0, t; }" : "=r"(a) : "l"(p));
    return a;
}
#define CP_ASYNC16(dst, src) \
    asm volatile("cp.async.cg.shared.global [%0], [%1], 16;" :: "r"(dst), "l"(src) : "memory")
#define CP_COMMIT()  asm volatile("cp.async.commit_group;" ::: "memory")
#define CP_WAIT1()   asm volatile("cp.async.wait_group 1;" ::: "memory")
#define CP_WAIT0()   asm volatile("cp.async.wait_group 0;" ::: "memory")

__device__ __forceinline__ void mma16816(float* d, const uint32_t* a, const uint32_t* b) {
    asm volatile("mma.sync.aligned.m16n8k16.row.col.f32.bf16.bf16.f32 "
        "{%0,%1,%2,%3}, {%4,%5,%6,%7}, {%8,%9}, {%0,%1,%2,%3};"
        : "+f"(d[0]), "+f"(d[1]), "+f"(d[2]), "+f"(d[3])
        : "r"(a[0]), "r"(a[1]), "r"(a[2]), "r"(a[3]), "r"(b[0]), "r"(b[1]));
}

#define LDSM4T(r, a) \
    asm volatile("ldmatrix.sync.aligned.m8n8.x4.trans.shared.b16 {%0,%1,%2,%3}, [%4];" \
        : "=r"((r)[0]), "=r"((r)[1]), "=r"((r)[2]), "=r"((r)[3]) : "r"(a))

// pack two fp32 into bf16x2 (hi) and their residuals into bf16x2 (lo)
__device__ __forceinline__ void splitpk(float x0, float x1, uint32_t& hi, uint32_t& lo) {
    bf16 h0 = __float2bfloat16(x0), h1 = __float2bfloat16(x1);
    __nv_bfloat162 th = __halves2bfloat162(h0, h1);
    hi = *(uint32_t*)&th;
    bf16 r0 = __float2bfloat16(x0 - __bfloat162float(h0));
    bf16 r1 = __float2bfloat16(x1 - __bfloat162float(h1));
    __nv_bfloat162 tl = __halves2bfloat162(r0, r1);
    lo = *(uint32_t*)&tl;
}

// ---------------- RoPE table ------------------------------------------------
__global__ void rope_table_kernel() {
    int i = blockIdx.x * blockDim.x + threadIdx.x;
    if (i >= Ss * 64) return;
    int s = i >> 6, j = i & 63;
    float e   = (float)(2 * j) / (float)HDd;
    float inv = 1.0f / powf(10000.0f, e);
    float ang = (float)s * inv;
    g_cos[i] = (float)cos((double)ang);
    g_sin[i] = (float)sin((double)ang);
}

// ---------------- fp32 -> bf16 hi/lo split ----------------------------------
__global__ __launch_bounds__(256) void cvt_split(const float* __restrict__ src,
                                                 bf16* __restrict__ hi,
                                                 bf16* __restrict__ lo, int n4) {
    int i = blockIdx.x * blockDim.x + threadIdx.x;
    if (i >= n4) return;
    float4 v = ((const float4*)src)[i];
    uint32_t h0, l0, h1, l1;
    splitpk(v.x, v.y, h0, l0);
    splitpk(v.z, v.w, h1, l1);
    ((uint32_t*)hi)[2 * i] = h0; ((uint32_t*)hi)[2 * i + 1] = h1;
    ((uint32_t*)lo)[2 * i] = l0; ((uint32_t*)lo)[2 * i + 1] = l1;
}

// ---------------- split-bf16 HMMA GEMM: C = A @ B^T (unchanged, proven) -----
#define LDA        40
#define ARRB       (128 * LDA * 2)
#define STAGEB     (4 * ARRB)
#define GEMM_SMEM  (2 * STAGEB)

__device__ __forceinline__ void gemm_load_chunk(
    uint32_t sm32, int buf, int tid, int c,
    const bf16* __restrict__ Ah, const bf16* __restrict__ Al,
    const bf16* __restrict__ Bh, const bf16* __restrict__ Bl,
    int bm, int bn, int K) {
    int row = tid >> 2;
    int t16 = tid & 3;
    uint32_t so = sm32 + buf * STAGEB + (uint32_t)row * 80 + (uint32_t)t16 * 16;
    size_t gA = (size_t)(bm + row) * K + (size_t)c * 32 + t16 * 8;
    size_t gB = (size_t)(bn + row) * K + (size_t)c * 32 + t16 * 8;
    size_t stp = (size_t)64 * K;
    CP_ASYNC16(so,                       Ah + gA);
    CP_ASYNC16(so + 64 * 80,             Ah + gA + stp);
    CP_ASYNC16(so + ARRB,                Al + gA);
    CP_ASYNC16(so + ARRB + 64 * 80,      Al + gA + stp);
    CP_ASYNC16(so + 2 * ARRB,            Bh + gB);
    CP_ASYNC16(so + 2 * ARRB + 64 * 80,  Bh + gB + stp);
    CP_ASYNC16(so + 3 * ARRB,            Bl + gB);
    CP_ASYNC16(so + 3 * ARRB + 64 * 80,  Bl + gB + stp);
}

__global__ __launch_bounds__(256) void gemm_bf16s(
    const bf16* __restrict__ Ah, const bf16* __restrict__ Al,
    const bf16* __restrict__ Bh, const bf16* __restrict__ Bl,
    float* __restrict__ C, int M, int N, int K) {
    extern __shared__ char sm[];
    const uint32_t sm32 = smem_u32(sm);
    const int tid  = threadIdx.x;
    const int wid  = tid >> 5, lane = tid & 31;
    const int lr   = lane >> 2, lc = lane & 3;
    const int wm   = wid & 1;
    const int wn   = wid >> 1;
    const int bm = blockIdx.y * 128, bn = blockIdx.x * 128;

    float acc[4][4][4];
#pragma unroll
    for (int i = 0; i < 4; i++)
#pragma unroll
        for (int j = 0; j < 4; j++)
#pragma unroll
            for (int r = 0; r < 4; r++) acc[i][j][r] = 0.0f;

    const int NC = K >> 5;
    gemm_load_chunk(sm32, 0, tid, 0, Ah, Al, Bh, Bl, bm, bn, K);
    CP_COMMIT();

    for (int c = 0; c < NC; c++) {
        const int buf = c & 1;
        if (c + 1 < NC) {
            gemm_load_chunk(sm32, buf ^ 1, tid, c + 1, Ah, Al, Bh, Bl, bm, bn, K);
            CP_COMMIT();
            CP_WAIT1();
        } else {
            CP_WAIT0();
        }
        __syncthreads();

        const bf16* sA  = (const bf16*)(sm + buf * STAGEB);
        const bf16* sAl = sA + 128 * LDA;
        const bf16* sB  = sA + 2 * 128 * LDA;
        const bf16* sBl = sA + 3 * 128 * LDA;
#pragma unroll
        for (int kst = 0; kst < 2; kst++) {
            const int pp = kst * 8 + lc;
            uint32_t ah[4][4], al[4][4], bh[4][2], bl[4][2];
#pragma unroll
            for (int mt = 0; mt < 4; mt++) {
                int r0 = wm * 64 + mt * 16 + lr;
                ah[mt][0] = *(const uint32_t*)(sA + r0 * LDA + pp * 2);
                ah[mt][1] = *(const uint32_t*)(sA + (r0 + 8) * LDA + pp * 2);
                ah[mt][2] = *(const uint32_t*)(sA + r0 * LDA + (pp + 4) * 2);
                ah[mt][3] = *(const uint32_t*)(sA + (r0 + 8) * LDA + (pp + 4) * 2);
                al[mt][0] = *(const uint32_t*)(sAl + r0 * LDA + pp * 2);
                al[mt][1] = *(const uint32_t*)(sAl + (r0 + 8) * LDA + pp * 2);
                al[mt][2] = *(const uint32_t*)(sAl + r0 * LDA + (pp + 4) * 2);
                al[mt][3] = *(const uint32_t*)(sAl + (r0 + 8) * LDA + (pp + 4) * 2);
            }
#pragma unroll
            for (int nt = 0; nt < 4; nt++) {
                int n0 = wn * 32 + nt * 8 + lr;
                bh[nt][0] = *(const uint32_t*)(sB + n0 * LDA + pp * 2);
                bh[nt][1] = *(const uint32_t*)(sB + n0 * LDA + (pp + 4) * 2);
                bl[nt][0] = *(const uint32_t*)(sBl + n0 * LDA + pp * 2);
                bl[nt][1] = *(const uint32_t*)(sBl + n0 * LDA + (pp + 4) * 2);
            }
#pragma unroll
            for (int mt = 0; mt < 4; mt++)
#pragma unroll
                for (int nt = 0; nt < 4; nt++) {
                    mma16816(acc[mt][nt], ah[mt], bh[nt]);
                    mma16816(acc[mt][nt], ah[mt], bl[nt]);
                    mma16816(acc[mt][nt], al[mt], bh[nt]);
                }
        }
        __syncthreads();
    }

#pragma unroll
    for (int mt = 0; mt < 4; mt++) {
        int m = bm + wm * 64 + mt * 16 + lr;
#pragma unroll
        for (int nt = 0; nt < 4; nt++) {
            int n = bn + wn * 32 + nt * 8 + lc * 2;
            *(float2*)(C + (size_t)m * N + n)       = make_float2(acc[mt][nt][0], acc[mt][nt][1]);
            *(float2*)(C + (size_t)(m + 8) * N + n) = make_float2(acc[mt][nt][2], acc[mt][nt][3]);
        }
    }
}

// ---------------- q/k epilogues: RMSNorm + RoPE (+gain) -> bf16 hi/lo -------
__global__ __launch_bounds__(256) void q_post(const float* __restrict__ gain,
                                              bf16* __restrict__ qh, bf16* __restrict__ ql) {
    int wid  = blockIdx.x * 8 + (threadIdx.x >> 5);
    int lane = threadIdx.x & 31;
    int h = wid & (Hh - 1);
    int s = (wid >> 4) & (Ss - 1);
    const float* base = g_q + (size_t)wid * 128;
    float e0 = base[lane], e1 = base[lane + 32], e2 = base[lane + 64], e3 = base[lane + 96];
    float ssum = e0 * e0 + e1 * e1 + e2 * e2 + e3 * e3;
#pragma unroll
    for (int o = 16; o > 0; o >>= 1) ssum += __shfl_xor_sync(0xffffffffu, ssum, o);
    float r = rsqrtf(ssum * (1.0f / 128.0f) + 1e-6f);
    float g = gain[h] * r * 0.08838834764831845f;
    float c0 = g_cos[s * 64 + lane],      sn0 = g_sin[s * 64 + lane];
    float c1 = g_cos[s * 64 + lane + 32], sn1 = g_sin[s * 64 + lane + 32];
    float o0 = ( e0 * c0  + e2 * sn0) * g;
    float o1 = ( e1 * c1  + e3 * sn1) * g;
    float o2 = (-e0 * sn0 + e2 * c0 ) * g;
    float o3 = (-e1 * sn1 + e3 * c1 ) * g;
    size_t off = (size_t)wid * 128;
    bf16 h0 = __float2bfloat16(o0); qh[off + lane]      = h0; ql[off + lane]      = __float2bfloat16(o0 - __bfloat162float(h0));
    bf16 h1 = __float2bfloat16(o1); qh[off + lane + 32] = h1; ql[off + lane + 32] = __float2bfloat16(o1 - __bfloat162float(h1));
    bf16 h2 = __float2bfloat16(o2); qh[off + lane + 64] = h2; ql[off + lane + 64] = __float2bfloat16(o2 - __bfloat162float(h2));
    bf16 h3 = __float2bfloat16(o3); qh[off + lane + 96] = h3; ql[off + lane + 96] = __float2bfloat16(o3 - __bfloat162float(h3));
}

__global__ __launch_bounds__(256) void k_post(bf16* __restrict__ kh, bf16* __restrict__ kl) {
    int wid  = blockIdx.x * 8 + (threadIdx.x >> 5);
    int lane = threadIdx.x & 31;
    int s = (wid >> 2) & (Ss - 1);
    const float* base = g_k + (size_t)wid * 128;
    float e0 = base[lane], e1 = base[lane + 32], e2 = base[lane + 64], e3 = base[lane + 96];
    float ssum = e0 * e0 + e1 * e1 + e2 * e2 + e3 * e3;
#pragma unroll
    for (int o = 16; o > 0; o >>= 1) ssum += __shfl_xor_sync(0xffffffffu, ssum, o);
    float r = rsqrtf(ssum * (1.0f / 128.0f) + 1e-6f);
    float c0 = g_cos[s * 64 + lane],      sn0 = g_sin[s * 64 + lane];
    float c1 = g_cos[s * 64 + lane + 32], sn1 = g_sin[s * 64 + lane + 32];
    float o0 = ( e0 * c0  + e2 * sn0) * r;
    float o1 = ( e1 * c1  + e3 * sn1) * r;
    float o2 = (-e0 * sn0 + e2 * c0 ) * r;
    float o3 = (-e1 * sn1 + e3 * c1 ) * r;
    size_t off = (size_t)wid * 128;
    bf16 h0 = __float2bfloat16(o0); kh[off + lane]      = h0; kl[off + lane]      = __float2bfloat16(o0 - __bfloat162float(h0));
    bf16 h1 = __float2bfloat16(o1); kh[off + lane + 32] = h1; kl[off + lane + 32] = __float2bfloat16(o1 - __bfloat162float(h1));
    bf16 h2 = __float2bfloat16(o2); kh[off + lane + 64] = h2; kl[off + lane + 64] = __float2bfloat16(o2 - __bfloat162float(h2));
    bf16 h3 = __float2bfloat16(o3); kh[off + lane + 96] = h3; kl[off + lane + 96] = __float2bfloat16(o3 - __bfloat162float(h3));
}

// ---------------- HMMA flash attention (split-bf16, FA2 layout) -------------
// 128 threads (4 warps), BM=BN=64. Warp w owns rows w*16..w*16+15.
// smem: Qh,Ql resident + 2-stage {Kh,Kl,Vh,Vl} cp.async pipeline. stride 136 bf16.
#define FST 136
#define FQE (64 * FST)
#define FL2_SMEM ((2 * FQE + 8 * FQE) * 2)   // 174080 bytes

__device__ __forceinline__ void fl_load_kv(uint32_t sbase, int tid, int b, int kvh, int k0,
    const bf16* __restrict__ Kh, const bf16* __restrict__ Kl,
    const bf16* __restrict__ Vh, const bf16* __restrict__ Vl) {
#pragma unroll
    for (int it = 0; it < 8; it++) {
        int c = tid + it * 128;
        int r = c >> 4, o16 = c & 15;
        uint32_t d = sbase + (uint32_t)r * (FST * 2) + o16 * 16;
        size_t g = ((size_t)((b * Ss + k0 + r) * KVHh + kvh)) * HDd + o16 * 8;
        CP_ASYNC16(d,               Kh + g);
        CP_ASYNC16(d + 2 * FQE,     Kl + g);
        CP_ASYNC16(d + 4 * FQE,     Vh + g);
        CP_ASYNC16(d + 6 * FQE,     Vl + g);
    }
}

__global__ __launch_bounds__(128) void flash2(
    const bf16* __restrict__ Qh, const bf16* __restrict__ Ql,
    const bf16* __restrict__ Kh, const bf16* __restrict__ Kl,
    const bf16* __restrict__ Vh, const bf16* __restrict__ Vl,
    bf16* __restrict__ Oh, bf16* __restrict__ Ol) {
    extern __shared__ bf16 smb[];
    bf16* sQh = smb;
    bf16* sQl = smb + FQE;
    const uint32_t sm32 = smem_u32(smb);
    const int tid = threadIdx.x, wid = tid >> 5, lane = tid & 31;
    const int lr = lane >> 2, lc = lane & 3;
    const int qt = (Ss / 64 - 1) - blockIdx.x;
    const int h = blockIdx.y, b = blockIdx.z, kvh = h >> 2;
    const int q0 = qt * 64;
    const int wrow = wid * 16;

    // Q tile -> smem (plain vector loads; covered by first __syncthreads)
#pragma unroll
    for (int it = 0; it < 8; it++) {
        int c = tid + it * 128;
        int r = c >> 4, o = (c & 15) * 8;
        size_t g = (size_t)(b * Ss + q0 + r) * Dd + h * HDd + o;
        *(uint4*)(sQh + r * FST + o) = *(const uint4*)(Qh + g);
        *(uint4*)(sQl + r * FST + o) = *(const uint4*)(Ql + g);
    }
    fl_load_kv(sm32 + 4 * FQE, tid, b, kvh, 0, Kh, Kl, Vh, Vl);
    CP_COMMIT();

    float m0 = -1e30f, m1 = -1e30f, l0 = 0.0f, l1 = 0.0f;
    float O[16][4];
#pragma unroll
    for (int i = 0; i < 16; i++) { O[i][0] = O[i][1] = O[i][2] = O[i][3] = 0.0f; }

    for (int kt = 0; kt <= qt; kt++) {
        const int stage = kt & 1;
        if (kt < qt) {
            fl_load_kv(sm32 + 4 * FQE + (stage ^ 1) * 8 * FQE, tid, b, kvh, (kt + 1) * 64,
                       Kh, Kl, Vh, Vl);
            CP_COMMIT();
            CP_WAIT1();
        } else {
            CP_WAIT0();
        }
        __syncthreads();

        const bf16* sKh = smb + 2 * FQE + stage * 4 * FQE;
        const bf16* sKl = sKh + FQE;
        const uint32_t vh32 = sm32 + (2 * FQE + stage * 4 * FQE + 2 * FQE) * 2;
        const uint32_t vl32 = vh32 + 2 * FQE;

        // ---- S = Q . K^T (3-term split) ----
        float S[8][4];
#pragma unroll
        for (int nt = 0; nt < 8; nt++) S[nt][0] = S[nt][1] = S[nt][2] = S[nt][3] = 0.0f;

#pragma unroll
        for (int kst = 0; kst < 8; kst++) {
            const int pp2 = kst * 16 + lc * 2;
            const int r0 = wrow + lr;
            uint32_t qa_h[4], qa_l[4];
            qa_h[0] = *(const uint32_t*)(sQh + r0 * FST + pp2);
            qa_h[1] = *(const uint32_t*)(sQh + (r0 + 8) * FST + pp2);
            qa_h[2] = *(const uint32_t*)(sQh + r0 * FST + pp2 + 8);
            qa_h[3] = *(const uint32_t*)(sQh + (r0 + 8) * FST + pp2 + 8);
            qa_l[0] = *(const uint32_t*)(sQl + r0 * FST + pp2);
            qa_l[1] = *(const uint32_t*)(sQl + (r0 + 8) * FST + pp2);
            qa_l[2] = *(const uint32_t*)(sQl + r0 * FST + pp2 + 8);
            qa_l[3] = *(const uint32_t*)(sQl + (r0 + 8) * FST + pp2 + 8);
#pragma unroll
            for (int nt = 0; nt < 8; nt++) {
                const int n0 = nt * 8 + lr;
                uint32_t kb[2], klb[2];
                kb[0]  = *(const uint32_t*)(sKh + n0 * FST + pp2);
                kb[1]  = *(const uint32_t*)(sKh + n0 * FST + pp2 + 8);
                klb[0] = *(const uint32_t*)(sKl + n0 * FST + pp2);
                klb[1] = *(const uint32_t*)(sKl + n0 * FST + pp2 + 8);
                mma16816(S[nt], qa_h, kb);
                mma16816(S[nt], qa_h, klb);
                mma16816(S[nt], qa_l, kb);
            }
        }

        if (kt == qt) {   // diagonal tile: mask col > row
            const int row0 = q0 + wrow + lr;
#pragma unroll
            for (int nt = 0; nt < 8; nt++) {
                const int col = kt * 64 + nt * 8 + lc * 2;
                if (col     > row0)     S[nt][0] = -1e30f;
                if (col + 1 > row0)     S[nt][1] = -1e30f;
                if (col     > row0 + 8) S[nt][2] = -1e30f;
                if (col + 1 > row0 + 8) S[nt][3] = -1e30f;
            }
        }

        // ---- online softmax (rows lr / lr+8; reduce over lanes lc via xor 1,2) ----
        float rm0 = -1e30f, rm1 = -1e30f;
#pragma unroll
        for (int nt = 0; nt < 8; nt++) {
            rm0 = fmaxf(rm0, fmaxf(S[nt][0], S[nt][1]));
            rm1 = fmaxf(rm1, fmaxf(S[nt][2], S[nt][3]));
        }
        rm0 = fmaxf(rm0, __shfl_xor_sync(0xffffffffu, rm0, 1));
        rm0 = fmaxf(rm0, __shfl_xor_sync(0xffffffffu, rm0, 2));
        rm1 = fmaxf(rm1, __shfl_xor_sync(0xffffffffu, rm1, 1));
        rm1 = fmaxf(rm1, __shfl_xor_sync(0xffffffffu, rm1, 2));
        float mn0 = fmaxf(m0, rm0), mn1 = fmaxf(m1, rm1);
        float a0 = __expf(m0 - mn0), a1 = __expf(m1 - mn1);
        float rs0 = 0.0f, rs1 = 0.0f;
#pragma unroll
        for (int nt = 0; nt < 8; nt++) {
            S[nt][0] = __expf(S[nt][0] - mn0);
            S[nt][1] = __expf(S[nt][1] - mn0);
            S[nt][2] = __expf(S[nt][2] - mn1);
            S[nt][3] = __expf(S[nt][3] - mn1);
            rs0 += S[nt][0] + S[nt][1];
            rs1 += S[nt][2] + S[nt][3];
        }
        rs0 += __shfl_xor_sync(0xffffffffu, rs0, 1);
        rs0 += __shfl_xor_sync(0xffffffffu, rs0, 2);
        rs1 += __shfl_xor_sync(0xffffffffu, rs1, 1);
        rs1 += __shfl_xor_sync(0xffffffffu, rs1, 2);
        l0 = l0 * a0 + rs0;
        l1 = l1 * a1 + rs1;
        m0 = mn0; m1 = mn1;
#pragma unroll
        for (int i = 0; i < 16; i++) {
            O[i][0] *= a0; O[i][1] *= a0; O[i][2] *= a1; O[i][3] *= a1;
        }

        // ---- P c-frags -> a-frags (hi/lo split) ----
        uint32_t pa_h[4][4], pa_l[4][4];
#pragma unroll
        for (int ks = 0; ks < 4; ks++) {
            splitpk(S[2 * ks][0],     S[2 * ks][1],     pa_h[ks][0], pa_l[ks][0]);
            splitpk(S[2 * ks][2],     S[2 * ks][3],     pa_h[ks][1], pa_l[ks][1]);
            splitpk(S[2 * ks + 1][0], S[2 * ks + 1][1], pa_h[ks][2], pa_l[ks][2]);
            splitpk(S[2 * ks + 1][2], S[2 * ks + 1][3], pa_h[ks][3], pa_l[ks][3]);
        }

        // ---- O += P . V (V b-frags via ldmatrix.x4.trans) ----
#pragma unroll
        for (int ks = 0; ks < 4; ks++) {
            const uint32_t va = ((uint32_t)(16 * ks + (lane & 15)) * FST) * 2 + (lane >> 4) * 16;
#pragma unroll
            for (int ntp = 0; ntp < 8; ntp++) {
                uint32_t vh4[4], vl4[4];
                LDSM4T(vh4, vh32 + va + ntp * 32);
                LDSM4T(vl4, vl32 + va + ntp * 32);
                uint32_t b0[2] = {vh4[0], vh4[1]}, b1[2] = {vh4[2], vh4[3]};
                uint32_t c0[2] = {vl4[0], vl4[1]}, c1[2] = {vl4[2], vl4[3]};
                mma16816(O[2 * ntp],     pa_h[ks], b0);
                mma16816(O[2 * ntp],     pa_l[ks], b0);
                mma16816(O[2 * ntp],     pa_h[ks], c0);
                mma16816(O[2 * ntp + 1], pa_h[ks], b1);
                mma16816(O[2 * ntp + 1], pa_l[ks], b1);
                mma16816(O[2 * ntp + 1], pa_h[ks], c1);
            }
        }
        __syncthreads();   // all warps done with this stage before next prefetch
    }

    // ---- epilogue: normalize, split to bf16 hi/lo, store in-place over Q ----
    float il0 = 1.0f / l0, il1 = 1.0f / l1;
    size_t r0 = (size_t)(b * Ss + q0 + wrow + lr) * Dd + h * HDd;
    size_t r1 = r0 + 8 * (size_t)Dd;
#pragma unroll
    for (int nt = 0; nt < 16; nt++) {
        int cc = nt * 8 + lc * 2;
        uint32_t h0, lo0, h1, lo1;
        splitpk(O[nt][0] * il0, O[nt][1] * il0, h0, lo0);
        splitpk(O[nt][2] * il1, O[nt][3] * il1, h1, lo1);
        *(uint32_t*)(Oh + r0 + cc) = h0; *(uint32_t*)(Ol + r0 + cc) = lo0;
        *(uint32_t*)(Oh + r1 + cc) = h1; *(uint32_t*)(Ol + r1 + cc) = lo1;
    }
}

// ---------------- launch ----------------------------------------------------
extern "C" void kernel_launch(void* const* d_in, const int* in_sizes, int n_in,
                              void* d_out, int out_size) {
    const float* x    = (const float*)d_in[0];
    const float* Wq   = (const float*)d_in[1];
    const float* Wk   = (const float*)d_in[2];
    const float* Wv   = (const float*)d_in[3];
    const float* Wp   = (const float*)d_in[4];
    const float* gain = (const float*)d_in[5];
    float* out = (float*)d_out;

    float *q, *k, *v;
    bf16 *xh, *xl, *wh, *wl, *kh, *kl, *vh, *vl;
    cudaGetSymbolAddress((void**)&q,  g_q);
    cudaGetSymbolAddress((void**)&k,  g_k);
    cudaGetSymbolAddress((void**)&v,  g_v);
    cudaGetSymbolAddress((void**)&xh, g_xh);
    cudaGetSymbolAddress((void**)&xl, g_xl);
    cudaGetSymbolAddress((void**)&wh, g_wh);
    cudaGetSymbolAddress((void**)&wl, g_wl);
    cudaGetSymbolAddress((void**)&kh, g_kh);
    cudaGetSymbolAddress((void**)&kl, g_kl);
    cudaGetSymbolAddress((void**)&vh, g_vh);
    cudaGetSymbolAddress((void**)&vl, g_vl);

    cudaFuncSetAttribute(gemm_bf16s, cudaFuncAttributeMaxDynamicSharedMemorySize, GEMM_SMEM);
    cudaFuncSetAttribute(flash2,     cudaFuncAttributeMaxDynamicSharedMemorySize, FL2_SMEM);

    const int M = Bb * Ss;                 // 4096
    const int n4x = M * Dd / 4;
    const int n4w = Dd * Dd / 4;
    const int n4k = KVHh * HDd * Dd / 4;
    const int n4v = Bb * Ss * KVHh * HDd / 4;

    rope_table_kernel<<<(Ss * 64 + 255) / 256, 256>>>();

    cvt_split<<<(n4x + 255) / 256, 256>>>(x, xh, xl, n4x);

    cvt_split<<<(n4w + 255) / 256, 256>>>(Wq, wh, wl, n4w);
    gemm_bf16s<<<dim3(Dd / 128, M / 128), 256, GEMM_SMEM>>>(xh, xl, wh, wl, q, M, Dd, Dd);

    cvt_split<<<(n4k + 255) / 256, 256>>>(Wk, wh, wl, n4k);
    gemm_bf16s<<<dim3((KVHh * HDd) / 128, M / 128), 256, GEMM_SMEM>>>(xh, xl, wh, wl, k, M, KVHh * HDd, Dd);

    cvt_split<<<(n4k + 255) / 256, 256>>>(Wv, wh, wl, n4k);
    gemm_bf16s<<<dim3((KVHh * HDd) / 128, M / 128), 256, GEMM_SMEM>>>(xh, xl, wh, wl, v, M, KVHh * HDd, Dd);

    // posts: overwrite xh/xl with Q split; k/v splits to their own buffers
    q_post<<<(Bb * Ss * Hh) / 8, 256>>>(gain, xh, xl);
    k_post<<<(Bb * Ss * KVHh) / 8, 256>>>(kh, kl);
    cvt_split<<<(n4v + 255) / 256, 256>>>(v, vh, vl, n4v);

    // flash reads Q from xh/xl, writes attention output split back into xh/xl
    flash2<<<dim3(Ss / 64, Hh, Bb), 128, FL2_SMEM>>>(xh, xl, kh, kl, vh, vl, xh, xl);

    cvt_split<<<(n4w + 255) / 256, 256>>>(Wp, wh, wl, n4w);
    gemm_bf16s<<<dim3(Dd / 128, M / 128), 256, GEMM_SMEM>>>(xh, xl, wh, wl, out, M, Dd, Dd);
}